// round 7
// baseline (speedup 1.0000x reference)
#include <cuda_runtime.h>
#include <cuda_bf16.h>

#define Bb 256
#define Tt 1024
#define INF 128
#define Hh 10
#define OUTD 128
#define BT (Bb*Tt)

typedef unsigned long long ull;

// Scratch (no cudaMalloc allowed): device globals
__device__ float g_xp0[(size_t)BT * Hh];   // [BT][10]
__device__ float g_out2[(size_t)BT * Hh];  // [BT][10]

// ---- packed f32x2 helpers (sm_103a) ----
__device__ __forceinline__ ull pk2(float a, float b) {
    ull r; asm("mov.b64 %0, {%1, %2};" : "=l"(r) : "f"(a), "f"(b)); return r;
}
__device__ __forceinline__ void fma2(ull& d, ull a, ull b, ull c) {
    asm("fma.rn.f32x2 %0, %1, %2, %3;" : "=l"(d) : "l"(a), "l"(b), "l"(c));
}
__device__ __forceinline__ void upk2(float& lo, float& hi, ull v) {
    asm("mov.b64 {%0, %1}, %2;" : "=f"(lo), "=f"(hi) : "l"(v));
}

// ---------------------------------------------------------------------------
// Kernel 1: xp0 = x @ W_ih0^T + b  (frozen from R6: 59us known)
// ---------------------------------------------------------------------------
__global__ __launch_bounds__(128) void k1_inproj(
    const float* __restrict__ x,
    const float* __restrict__ W_ih0,
    const float* __restrict__ b_ih0,
    const float* __restrict__ b_hh0)
{
    __shared__ float xs[128 * 129];
    __shared__ float4 Wq[128][3];
    __shared__ float bs[16];
    int tid = threadIdx.x;
    for (int i = tid; i < 128 * 3; i += 128) {
        int f = i / 3, g = i % 3;
        float4 v;
        v.x = (4*g+0 < Hh) ? W_ih0[(4*g+0)*128 + f] : 0.f;
        v.y = (4*g+1 < Hh) ? W_ih0[(4*g+1)*128 + f] : 0.f;
        v.z = (4*g+2 < Hh) ? W_ih0[(4*g+2)*128 + f] : 0.f;
        v.w = (4*g+3 < Hh) ? W_ih0[(4*g+3)*128 + f] : 0.f;
        Wq[f][g] = v;
    }
    if (tid < Hh) bs[tid] = b_ih0[tid] + b_hh0[tid];

    const float* xrow = x + (size_t)blockIdx.x * 128 * 128;
    #pragma unroll 16
    for (int i = tid; i < 128 * 128; i += 128) {
        xs[(i >> 7) * 129 + (i & 127)] = xrow[i];
    }
    __syncthreads();

    float acc[Hh];
    #pragma unroll
    for (int h = 0; h < Hh; h++) acc[h] = bs[h];

    const float* xr = xs + tid * 129;
    #pragma unroll 8
    for (int f = 0; f < 128; f++) {
        float xv = xr[f];
        float4 wa = Wq[f][0], wb = Wq[f][1], wc = Wq[f][2];
        acc[0] = fmaf(xv, wa.x, acc[0]);
        acc[1] = fmaf(xv, wa.y, acc[1]);
        acc[2] = fmaf(xv, wa.z, acc[2]);
        acc[3] = fmaf(xv, wa.w, acc[3]);
        acc[4] = fmaf(xv, wb.x, acc[4]);
        acc[5] = fmaf(xv, wb.y, acc[5]);
        acc[6] = fmaf(xv, wb.z, acc[6]);
        acc[7] = fmaf(xv, wb.w, acc[7]);
        acc[8] = fmaf(xv, wc.x, acc[8]);
        acc[9] = fmaf(xv, wc.y, acc[9]);
    }
    __syncthreads();
    float* os = xs;                          // [128][12]
    #pragma unroll
    for (int h = 0; h < Hh; h++) os[tid * 12 + h] = acc[h];
    __syncthreads();

    float4* g4 = (float4*)(g_xp0 + (size_t)blockIdx.x * 128 * Hh);
    for (int i = tid; i < 320; i += 128) {
        int e = i * 4;
        float4 v;
        v.x = os[(e    ) / 10 * 12 + (e    ) % 10];
        v.y = os[(e + 1) / 10 * 12 + (e + 1) % 10];
        v.z = os[(e + 2) / 10 * 12 + (e + 2) % 10];
        v.w = os[(e + 3) / 10 * 12 + (e + 3) % 10];
        g4[i] = v;
    }
}

// ---------------------------------------------------------------------------
// Kernel 2: lockstep bar-pipelined 2-layer ReLU RNN scan. ZERO shfls.
// warp0 (producer, layer 0) and warp1 (consumer, layer 1 one step behind)
// advance with ONE bar.sync per step; h vectors broadcast through ping-pong
// smem rows (STS -> bar -> 5x LDS.64 next step). All parities compile-time.
// Dots in packed fma.rn.f32x2 (halves FMA instruction count).
// ---------------------------------------------------------------------------
__global__ __launch_bounds__(64) void k2_scan(
    const float* __restrict__ W_hh0,
    const float* __restrict__ W_ih1,
    const float* __restrict__ W_hh1,
    const float* __restrict__ b_ih1,
    const float* __restrict__ b_hh1,
    float* __restrict__ dout)
{
    __shared__ float h0buf[2][12];
    __shared__ float h1buf[2][12];
    int tid  = threadIdx.x;
    int wip  = tid >> 5;
    int lane = tid & 31;
    int j    = lane < Hh ? lane : Hh - 1;
    int batch = blockIdx.x;

    if (tid < 12) {
        h0buf[0][tid] = 0.f; h0buf[1][tid] = 0.f;
        h1buf[0][tid] = 0.f; h1buf[1][tid] = 0.f;
    }
    __syncthreads();

    float* hid = dout + (size_t)BT * OUTD;   // hidden: [2][B][H]

    if (wip == 0) {
        // ---------------- producer: layer 0 ----------------
        ull w0p[5];
        #pragma unroll
        for (int i = 0; i < 5; i++)
            w0p[i] = pk2(W_hh0[j * Hh + 2*i], W_hh0[j * Hh + 2*i + 1]);

        const float* xp = g_xp0 + (size_t)batch * Tt * Hh;
        float xa[8], xb[8];
        #pragma unroll
        for (int d = 0; d < 8; d++) xa[d] = xp[d * Hh + j];

        float h0n = 0.f;
        for (int g = 0; g < 128; g++) {
            if (g < 127) {
                #pragma unroll
                for (int d = 0; d < 8; d++)
                    xb[d] = xp[((g + 1) * 8 + d) * Hh + j];
            }
            #pragma unroll
            for (int d = 0; d < 8; d++) {
                // read v0 = h0[t-1] from slot (t-1)&1 = (d+1)&1
                const ull* v0p = (const ull*)h0buf[(d + 1) & 1];
                ull acc = pk2(xa[d], 0.f);
                fma2(acc, w0p[0], v0p[0], acc);
                fma2(acc, w0p[1], v0p[1], acc);
                fma2(acc, w0p[2], v0p[2], acc);
                fma2(acc, w0p[3], v0p[3], acc);
                fma2(acc, w0p[4], v0p[4], acc);
                float lo, hi; upk2(lo, hi, acc);
                h0n = fmaxf(lo + hi, 0.f);
                if (lane < Hh) h0buf[d & 1][lane] = h0n;   // slot t&1
                asm volatile("bar.sync 0;" ::: "memory");
            }
            #pragma unroll
            for (int d = 0; d < 8; d++) xa[d] = xb[d];
        }
        if (lane < Hh) hid[batch * Hh + lane] = h0n;       // h0[T-1]
    } else {
        // ---------------- consumer: layer 1, one step behind ----------------
        ull wi1p[5], w1p[5];
        #pragma unroll
        for (int i = 0; i < 5; i++) {
            wi1p[i] = pk2(W_ih1[j * Hh + 2*i], W_ih1[j * Hh + 2*i + 1]);
            w1p[i]  = pk2(W_hh1[j * Hh + 2*i], W_hh1[j * Hh + 2*i + 1]);
        }
        float bias1 = b_ih1[j] + b_hh1[j];
        float* o2 = g_out2 + (size_t)batch * Tt * Hh;
        float h1n = 0.f;

        // group 0: t = 0..7, compute h1[t-1] only for t >= 1
        #pragma unroll
        for (int d = 0; d < 8; d++) {
            if (d > 0) {    // compile-time after unroll
                const ull* v0p = (const ull*)h0buf[(d + 1) & 1]; // h0[t-1]
                const ull* v1p = (const ull*)h1buf[d & 1];       // h1[t-2]
                ull a0 = pk2(bias1, 0.f), a1 = 0ULL;
                fma2(a0, wi1p[0], v0p[0], a0);
                fma2(a1, w1p[0],  v1p[0], a1);
                fma2(a0, wi1p[1], v0p[1], a0);
                fma2(a1, w1p[1],  v1p[1], a1);
                fma2(a0, wi1p[2], v0p[2], a0);
                fma2(a1, w1p[2],  v1p[2], a1);
                fma2(a0, wi1p[3], v0p[3], a0);
                fma2(a1, w1p[3],  v1p[3], a1);
                fma2(a0, wi1p[4], v0p[4], a0);
                fma2(a1, w1p[4],  v1p[4], a1);
                float l0, u0, l1, u1;
                upk2(l0, u0, a0); upk2(l1, u1, a1);
                h1n = fmaxf((l0 + u0) + (l1 + u1), 0.f);
                if (lane < Hh) {
                    h1buf[(d + 1) & 1][lane] = h1n;              // slot (t-1)&1
                    o2[(size_t)(d - 1) * Hh + lane] = h1n;
                }
            }
            asm volatile("bar.sync 0;" ::: "memory");
        }

        for (int g = 1; g < 128; g++) {
            #pragma unroll
            for (int d = 0; d < 8; d++) {
                int t = g * 8 + d;
                const ull* v0p = (const ull*)h0buf[(d + 1) & 1];
                const ull* v1p = (const ull*)h1buf[d & 1];
                ull a0 = pk2(bias1, 0.f), a1 = 0ULL;
                fma2(a0, wi1p[0], v0p[0], a0);
                fma2(a1, w1p[0],  v1p[0], a1);
                fma2(a0, wi1p[1], v0p[1], a0);
                fma2(a1, w1p[1],  v1p[1], a1);
                fma2(a0, wi1p[2], v0p[2], a0);
                fma2(a1, w1p[2],  v1p[2], a1);
                fma2(a0, wi1p[3], v0p[3], a0);
                fma2(a1, w1p[3],  v1p[3], a1);
                fma2(a0, wi1p[4], v0p[4], a0);
                fma2(a1, w1p[4],  v1p[4], a1);
                float l0, u0, l1, u1;
                upk2(l0, u0, a0); upk2(l1, u1, a1);
                h1n = fmaxf((l0 + u0) + (l1 + u1), 0.f);
                if (lane < Hh) {
                    h1buf[(d + 1) & 1][lane] = h1n;
                    o2[(size_t)(t - 1) * Hh + lane] = h1n;
                }
                asm volatile("bar.sync 0;" ::: "memory");
            }
        }

        // epilogue: t = 1024 -> h1[1023]. v0 slot 1 (h0[1023]), v1 slot 0.
        {
            const ull* v0p = (const ull*)h0buf[1];
            const ull* v1p = (const ull*)h1buf[0];
            ull a0 = pk2(bias1, 0.f), a1 = 0ULL;
            #pragma unroll
            for (int i = 0; i < 5; i++) {
                fma2(a0, wi1p[i], v0p[i], a0);
                fma2(a1, w1p[i],  v1p[i], a1);
            }
            float l0, u0, l1, u1;
            upk2(l0, u0, a0); upk2(l1, u1, a1);
            h1n = fmaxf((l0 + u0) + (l1 + u1), 0.f);
            if (lane < Hh) {
                o2[(size_t)(Tt - 1) * Hh + lane] = h1n;
                hid[Bb * Hh + batch * Hh + lane] = h1n;          // h1[T-1]
            }
        }
    }
}

// ---------------------------------------------------------------------------
// Kernel 3: logits = out2 @ W_lin^T + b_lin, softmax over 128. (frozen)
// ---------------------------------------------------------------------------
__global__ __launch_bounds__(256) void k3_head(
    const float* __restrict__ W_lin,
    const float* __restrict__ b_lin,
    float* __restrict__ out)
{
    const unsigned FULL = 0xffffffffu;
    __shared__ float Wl[OUTD * Hh];
    __shared__ float bl[OUTD];
    int tid = threadIdx.x;
    for (int i = tid; i < OUTD * Hh; i += blockDim.x) Wl[i] = W_lin[i];
    for (int i = tid; i < OUTD; i += blockDim.x) bl[i] = b_lin[i];
    __syncthreads();

    int lane = tid & 31;
    int wib  = tid >> 5;
    float wl[4][Hh], bb[4];
    #pragma unroll
    for (int c = 0; c < 4; c++) {
        int o = 4 * lane + c;
        bb[c] = bl[o];
        #pragma unroll
        for (int k = 0; k < Hh; k++) wl[c][k] = Wl[o * Hh + k];
    }

    int wpb = blockDim.x >> 5;
    int gw  = blockIdx.x * wpb + wib;
    int nw  = gridDim.x * wpb;
    for (int row = gw; row < BT; row += nw) {
        float v = g_out2[(size_t)row * Hh + (lane < Hh ? lane : 0)];
        float hk[Hh];
        #pragma unroll
        for (int k = 0; k < Hh; k++) hk[k] = __shfl_sync(FULL, v, k);

        float acc[4];
        #pragma unroll
        for (int c = 0; c < 4; c++) {
            acc[c] = bb[c];
            #pragma unroll
            for (int k = 0; k < Hh; k++) acc[c] = fmaf(hk[k], wl[c][k], acc[c]);
        }
        float m = fmaxf(fmaxf(acc[0], acc[1]), fmaxf(acc[2], acc[3]));
        #pragma unroll
        for (int s = 16; s > 0; s >>= 1)
            m = fmaxf(m, __shfl_xor_sync(FULL, m, s));
        float e0 = __expf(acc[0] - m), e1 = __expf(acc[1] - m);
        float e2 = __expf(acc[2] - m), e3 = __expf(acc[3] - m);
        float s = e0 + e1 + e2 + e3;
        #pragma unroll
        for (int sh = 16; sh > 0; sh >>= 1)
            s += __shfl_xor_sync(FULL, s, sh);
        float r = __frcp_rn(s);
        float4 res = make_float4(e0 * r, e1 * r, e2 * r, e3 * r);
        ((float4*)(out + (size_t)row * OUTD))[lane] = res;
    }
}

// ---------------------------------------------------------------------------
extern "C" void kernel_launch(void* const* d_in, const int* in_sizes, int n_in,
                              void* d_out, int out_size)
{
    const float* x      = (const float*)d_in[0];
    const float* W_ih0  = (const float*)d_in[1];
    const float* W_hh0  = (const float*)d_in[2];
    const float* b_ih0  = (const float*)d_in[3];
    const float* b_hh0  = (const float*)d_in[4];
    const float* W_ih1  = (const float*)d_in[5];
    const float* W_hh1  = (const float*)d_in[6];
    const float* b_ih1  = (const float*)d_in[7];
    const float* b_hh1  = (const float*)d_in[8];
    const float* W_lin  = (const float*)d_in[9];
    const float* b_lin  = (const float*)d_in[10];
    float* out = (float*)d_out;

    k1_inproj<<<2048, 128>>>(x, W_ih0, b_ih0, b_hh0);
    k2_scan<<<Bb, 64>>>(W_hh0, W_ih1, W_hh1, b_ih1, b_hh1, out);
    k3_head<<<2048, 256>>>(W_lin, b_lin, out);
}

// round 8
// speedup vs baseline: 1.0541x; 1.0541x over previous
#include <cuda_runtime.h>
#include <cuda_bf16.h>

#define Bb 256
#define Tt 1024
#define INF 128
#define Hh 10
#define OUTD 128
#define BT (Bb*Tt)

typedef unsigned long long ull;

// Scratch (no cudaMalloc allowed): device globals
__device__ float g_xp0[(size_t)BT * Hh];   // [BT][10]
__device__ float g_out2[(size_t)BT * Hh];  // [BT][10]

// ---- packed f32x2 helpers (sm_103a) ----
__device__ __forceinline__ ull pk2(float a, float b) {
    ull r; asm("mov.b64 %0, {%1, %2};" : "=l"(r) : "f"(a), "f"(b)); return r;
}
__device__ __forceinline__ void fma2(ull& d, ull a, ull b, ull c) {
    asm("fma.rn.f32x2 %0, %1, %2, %3;" : "=l"(d) : "l"(a), "l"(b), "l"(c));
}
__device__ __forceinline__ void upk2(float& lo, float& hi, ull v) {
    asm("mov.b64 {%0, %1}, %2;" : "=f"(lo), "=f"(hi) : "l"(v));
}

// ---------------------------------------------------------------------------
// Kernel 1: xp0 = x @ W_ih0^T + b. Coalesced smem-staged tiles + f32x2 FMAs
// (halves FMA instruction count; per-SMSP bound drops FMA->LDS).
// ---------------------------------------------------------------------------
__global__ __launch_bounds__(128) void k1_inproj(
    const float* __restrict__ x,
    const float* __restrict__ W_ih0,
    const float* __restrict__ b_ih0,
    const float* __restrict__ b_hh0)
{
    __shared__ float xs[128 * 129];
    __shared__ ull  Wp[128][5];              // Wp[f][p] = (W[2p][f], W[2p+1][f])
    __shared__ float bs[16];
    int tid = threadIdx.x;
    for (int i = tid; i < 128 * 5; i += 128) {
        int f = i / 5, p = i % 5;
        Wp[f][p] = pk2(W_ih0[(2*p) * 128 + f], W_ih0[(2*p+1) * 128 + f]);
    }
    if (tid < Hh) bs[tid] = b_ih0[tid] + b_hh0[tid];

    const float* xrow = x + (size_t)blockIdx.x * 128 * 128;
    #pragma unroll 16
    for (int i = tid; i < 128 * 128; i += 128) {
        xs[(i >> 7) * 129 + (i & 127)] = xrow[i];
    }
    __syncthreads();

    ull A[5];
    #pragma unroll
    for (int p = 0; p < 5; p++) A[p] = pk2(bs[2*p], bs[2*p+1]);

    const float* xr = xs + tid * 129;
    #pragma unroll 8
    for (int f = 0; f < 128; f++) {
        float xv = xr[f];
        ull xd = pk2(xv, xv);
        fma2(A[0], xd, Wp[f][0], A[0]);
        fma2(A[1], xd, Wp[f][1], A[1]);
        fma2(A[2], xd, Wp[f][2], A[2]);
        fma2(A[3], xd, Wp[f][3], A[3]);
        fma2(A[4], xd, Wp[f][4], A[4]);
    }
    float acc[Hh];
    #pragma unroll
    for (int p = 0; p < 5; p++) upk2(acc[2*p], acc[2*p+1], A[p]);

    __syncthreads();
    float* os = xs;                          // [128][12]
    #pragma unroll
    for (int h = 0; h < Hh; h++) os[tid * 12 + h] = acc[h];
    __syncthreads();

    float4* g4 = (float4*)(g_xp0 + (size_t)blockIdx.x * 128 * Hh);
    for (int i = tid; i < 320; i += 128) {
        int e = i * 4;
        float4 v;
        v.x = os[(e    ) / 10 * 12 + (e    ) % 10];
        v.y = os[(e + 1) / 10 * 12 + (e + 1) % 10];
        v.z = os[(e + 2) / 10 * 12 + (e + 2) % 10];
        v.w = os[(e + 3) / 10 * 12 + (e + 3) % 10];
        g4[i] = v;
    }
}

// ---------------------------------------------------------------------------
// Kernel 2: warp-specialized scan, group-granular polling (R6 skeleton),
// ZERO shfls: producer re-reads its own buf[t-1] row via broadcast LDS.64;
// consumer keeps h1[t-1] in a 2-slot smem ring (STS + LDS.64, compile-time
// parity). One __syncwarp per step orders intra-warp STS->LDS. f32x2 math.
// ---------------------------------------------------------------------------
__global__ __launch_bounds__(64) void k2_scan(
    const float* __restrict__ W_hh0,
    const float* __restrict__ W_ih1,
    const float* __restrict__ W_hh1,
    const float* __restrict__ b_ih1,
    const float* __restrict__ b_hh1,
    float* __restrict__ dout)
{
    extern __shared__ float buf[];          // [1024][12] : h0 stream
    __shared__ float h1ring[2][12];
    __shared__ int prog_s[8];
    int tid  = threadIdx.x;
    int wip  = tid >> 5;
    int lane = tid & 31;
    int j    = lane < Hh ? lane : Hh - 1;
    int batch = blockIdx.x;
    volatile int* pprog = &prog_s[0];

    if (tid < 12) { h1ring[0][tid] = 0.f; h1ring[1][tid] = 0.f; }
    if (tid == 0) prog_s[0] = 0;
    __syncthreads();

    float* hid = dout + (size_t)BT * OUTD;   // hidden: [2][B][H]

    if (wip == 0) {
        // ---------------- producer: layer 0 ----------------
        ull w0p[5];
        #pragma unroll
        for (int i = 0; i < 5; i++)
            w0p[i] = pk2(W_hh0[j * Hh + 2*i], W_hh0[j * Hh + 2*i + 1]);

        const float* xp = g_xp0 + (size_t)batch * Tt * Hh;
        float xa[8], xb[8];
        #pragma unroll
        for (int d = 0; d < 8; d++) xa[d] = xp[d * Hh + j];

        // ---- group 0 (t = 0 peeled: v0 = 0) ----
        float h0n = fmaxf(xa[0], 0.f);
        if (lane < Hh) buf[0 * 12 + lane] = h0n;
        #pragma unroll
        for (int d = 1; d < 8; d++) {
            __syncwarp();
            const ull* v0p = (const ull*)(buf + (d - 1) * 12);
            ull acc = pk2(xa[d], 0.f);
            fma2(acc, w0p[0], v0p[0], acc);
            fma2(acc, w0p[1], v0p[1], acc);
            fma2(acc, w0p[2], v0p[2], acc);
            fma2(acc, w0p[3], v0p[3], acc);
            fma2(acc, w0p[4], v0p[4], acc);
            float lo, hi; upk2(lo, hi, acc);
            h0n = fmaxf(lo + hi, 0.f);
            if (lane < Hh) buf[d * 12 + lane] = h0n;
        }
        __threadfence_block();
        if (lane == 0) *pprog = 8;
        #pragma unroll
        for (int d = 0; d < 8; d++) xa[d] = xp[(8 + d) * Hh + j];

        for (int g = 1; g < 128; g++) {
            if (g < 127) {
                #pragma unroll
                for (int d = 0; d < 8; d++)
                    xb[d] = xp[((g + 1) * 8 + d) * Hh + j];
            }
            #pragma unroll
            for (int d = 0; d < 8; d++) {
                int t = g * 8 + d;
                __syncwarp();
                const ull* v0p = (const ull*)(buf + (t - 1) * 12);
                ull acc = pk2(xa[d], 0.f);
                fma2(acc, w0p[0], v0p[0], acc);
                fma2(acc, w0p[1], v0p[1], acc);
                fma2(acc, w0p[2], v0p[2], acc);
                fma2(acc, w0p[3], v0p[3], acc);
                fma2(acc, w0p[4], v0p[4], acc);
                float lo, hi; upk2(lo, hi, acc);
                h0n = fmaxf(lo + hi, 0.f);
                if (lane < Hh) buf[t * 12 + lane] = h0n;
            }
            __threadfence_block();
            if (lane == 0) *pprog = g * 8 + 8;
            #pragma unroll
            for (int d = 0; d < 8; d++) xa[d] = xb[d];
        }
        if (lane < Hh) hid[batch * Hh + lane] = h0n;       // h0[T-1]
    } else {
        // ---------------- consumer: layer 1 ----------------
        ull wi1p[5], w1p[5];
        #pragma unroll
        for (int i = 0; i < 5; i++) {
            wi1p[i] = pk2(W_ih1[j * Hh + 2*i], W_ih1[j * Hh + 2*i + 1]);
            w1p[i]  = pk2(W_hh1[j * Hh + 2*i], W_hh1[j * Hh + 2*i + 1]);
        }
        float bias1 = b_ih1[j] + b_hh1[j];
        float* o2 = g_out2 + (size_t)batch * Tt * Hh;
        float h1n = 0.f;

        int seen = 0;
        while ((seen = *pprog) < 8) { }
        __threadfence_block();
        ull c[5];
        {
            const ull* cb = (const ull*)buf;     // h0[0]
            #pragma unroll
            for (int i = 0; i < 5; i++) c[i] = cb[i];
        }

        for (int g = 0; g < 128; g++) {
            #pragma unroll
            for (int d = 0; d < 8; d++) {
                int t = g * 8 + d;
                ull n[5];
                if (d < 7) {                 // compile-time prefetch
                    const ull* nb = (const ull*)(buf + (t + 1) * 12);
                    #pragma unroll
                    for (int i = 0; i < 5; i++) n[i] = nb[i];
                }
                __syncwarp();
                // v1 = h1[t-1] from ring slot (t-1)&1 = (d+1)&1
                const ull* v1p = (const ull*)h1ring[(d + 1) & 1];
                ull a0 = pk2(bias1, 0.f), a1 = 0ULL;
                fma2(a0, wi1p[0], c[0], a0);
                fma2(a1, w1p[0],  v1p[0], a1);
                fma2(a0, wi1p[1], c[1], a0);
                fma2(a1, w1p[1],  v1p[1], a1);
                fma2(a0, wi1p[2], c[2], a0);
                fma2(a1, w1p[2],  v1p[2], a1);
                fma2(a0, wi1p[3], c[3], a0);
                fma2(a1, w1p[3],  v1p[3], a1);
                fma2(a0, wi1p[4], c[4], a0);
                fma2(a1, w1p[4],  v1p[4], a1);
                float l0, u0, l1, u1;
                upk2(l0, u0, a0); upk2(l1, u1, a1);
                h1n = fmaxf((l0 + u0) + (l1 + u1), 0.f);
                if (lane < Hh) {
                    h1ring[d & 1][lane] = h1n;           // slot t&1
                    o2[(size_t)t * Hh + lane] = h1n;
                }
                if (d < 7) {
                    #pragma unroll
                    for (int i = 0; i < 5; i++) c[i] = n[i];
                }
            }
            if (g < 127) {
                int need = (g + 1) * 8 + 8;
                if (seen < need) {
                    while ((seen = *pprog) < need) { }
                    __threadfence_block();
                }
                const ull* nb = (const ull*)(buf + (g + 1) * 8 * 12);
                #pragma unroll
                for (int i = 0; i < 5; i++) c[i] = nb[i];
            }
        }
        if (lane < Hh) hid[Bb * Hh + batch * Hh + lane] = h1n;   // h1[T-1]
    }
}

// ---------------------------------------------------------------------------
// Kernel 3: logits = out2 @ W_lin^T + b_lin, softmax over 128. (frozen)
// ---------------------------------------------------------------------------
__global__ __launch_bounds__(256) void k3_head(
    const float* __restrict__ W_lin,
    const float* __restrict__ b_lin,
    float* __restrict__ out)
{
    const unsigned FULL = 0xffffffffu;
    __shared__ float Wl[OUTD * Hh];
    __shared__ float bl[OUTD];
    int tid = threadIdx.x;
    for (int i = tid; i < OUTD * Hh; i += blockDim.x) Wl[i] = W_lin[i];
    for (int i = tid; i < OUTD; i += blockDim.x) bl[i] = b_lin[i];
    __syncthreads();

    int lane = tid & 31;
    int wib  = tid >> 5;
    float wl[4][Hh], bb[4];
    #pragma unroll
    for (int c = 0; c < 4; c++) {
        int o = 4 * lane + c;
        bb[c] = bl[o];
        #pragma unroll
        for (int k = 0; k < Hh; k++) wl[c][k] = Wl[o * Hh + k];
    }

    int wpb = blockDim.x >> 5;
    int gw  = blockIdx.x * wpb + wib;
    int nw  = gridDim.x * wpb;
    for (int row = gw; row < BT; row += nw) {
        float v = g_out2[(size_t)row * Hh + (lane < Hh ? lane : 0)];
        float hk[Hh];
        #pragma unroll
        for (int k = 0; k < Hh; k++) hk[k] = __shfl_sync(FULL, v, k);

        float acc[4];
        #pragma unroll
        for (int c = 0; c < 4; c++) {
            acc[c] = bb[c];
            #pragma unroll
            for (int k = 0; k < Hh; k++) acc[c] = fmaf(hk[k], wl[c][k], acc[c]);
        }
        float m = fmaxf(fmaxf(acc[0], acc[1]), fmaxf(acc[2], acc[3]));
        #pragma unroll
        for (int s = 16; s > 0; s >>= 1)
            m = fmaxf(m, __shfl_xor_sync(FULL, m, s));
        float e0 = __expf(acc[0] - m), e1 = __expf(acc[1] - m);
        float e2 = __expf(acc[2] - m), e3 = __expf(acc[3] - m);
        float s = e0 + e1 + e2 + e3;
        #pragma unroll
        for (int sh = 16; sh > 0; sh >>= 1)
            s += __shfl_xor_sync(FULL, s, sh);
        float r = __frcp_rn(s);
        float4 res = make_float4(e0 * r, e1 * r, e2 * r, e3 * r);
        ((float4*)(out + (size_t)row * OUTD))[lane] = res;
    }
}

// ---------------------------------------------------------------------------
extern "C" void kernel_launch(void* const* d_in, const int* in_sizes, int n_in,
                              void* d_out, int out_size)
{
    const float* x      = (const float*)d_in[0];
    const float* W_ih0  = (const float*)d_in[1];
    const float* W_hh0  = (const float*)d_in[2];
    const float* b_ih0  = (const float*)d_in[3];
    const float* b_hh0  = (const float*)d_in[4];
    const float* W_ih1  = (const float*)d_in[5];
    const float* W_hh1  = (const float*)d_in[6];
    const float* b_ih1  = (const float*)d_in[7];
    const float* b_hh1  = (const float*)d_in[8];
    const float* W_lin  = (const float*)d_in[9];
    const float* b_lin  = (const float*)d_in[10];
    float* out = (float*)d_out;

    const int k2_smem = Tt * 12 * sizeof(float);   // 48KB
    cudaFuncSetAttribute(k2_scan, cudaFuncAttributeMaxDynamicSharedMemorySize,
                         k2_smem);

    k1_inproj<<<2048, 128>>>(x, W_ih0, b_ih0, b_hh0);
    k2_scan<<<Bb, 64, k2_smem>>>(W_hh0, W_ih1, W_hh1, b_ih1, b_hh1, out);
    k3_head<<<2048, 256>>>(W_lin, b_lin, out);
}